// round 12
// baseline (speedup 1.0000x reference)
#include <cuda_runtime.h>
#include <cuda_bf16.h>
#include <math.h>
#include <stdint.h>

// Problem constants
#define BATCH   2
#define SEQ     2048
#define DIN     2048
#define DOUT    2048
#define NHEADS  32
#define NKV     8
#define HD      64
#define MROWS   (BATCH * SEQ)      // 4096
#define NKVD    (NKV * HD)         // 512

// Scratch (allocation-free rule: __device__ globals)
__device__ float g_q[(size_t)BATCH * NHEADS * SEQ * HD];   // 32MB
__device__ float g_k[(size_t)BATCH * NKV * SEQ * HD];      //  8MB
__device__ float g_v[(size_t)BATCH * NKV * SEQ * HD];      //  8MB
__device__ float g_ctx[(size_t)MROWS * DOUT];              // 32MB (tf32-rounded)
__device__ float g_xr[(size_t)MROWS * DIN];                // 32MB x, tf32-rounded
__device__ float g_wqT[(size_t)DOUT * DIN];                // 16MB [N][K], rounded
__device__ float g_wkT[(size_t)NKVD * DIN];                //  4MB
__device__ float g_wvT[(size_t)NKVD * DIN];                //  4MB
__device__ float g_woT[(size_t)DOUT * DIN];                // 16MB

// ----------------------------------------------------------------------------
// Helpers
// ----------------------------------------------------------------------------
__device__ __forceinline__ float to_tf32(float x) {
    uint32_t u;
    asm("cvt.rna.tf32.f32 %0, %1;" : "=r"(u) : "f"(x));
    return __uint_as_float(u);
}

__device__ __forceinline__ void mma_tf32(float c[4],
                                         uint32_t a0, uint32_t a1, uint32_t a2, uint32_t a3,
                                         uint32_t b0, uint32_t b1) {
    asm volatile(
        "mma.sync.aligned.m16n8k8.row.col.f32.tf32.tf32.f32 "
        "{%0,%1,%2,%3}, {%4,%5,%6,%7}, {%8,%9}, {%0,%1,%2,%3};"
        : "+f"(c[0]), "+f"(c[1]), "+f"(c[2]), "+f"(c[3])
        : "r"(a0), "r"(a1), "r"(a2), "r"(a3), "r"(b0), "r"(b1));
}

__device__ __forceinline__ void ldsm_x4(uint32_t& r0, uint32_t& r1,
                                        uint32_t& r2, uint32_t& r3, uint32_t addr) {
    asm volatile("ldmatrix.sync.aligned.m8n8.x4.shared.b16 {%0,%1,%2,%3}, [%4];"
                 : "=r"(r0), "=r"(r1), "=r"(r2), "=r"(r3) : "r"(addr));
}

__device__ __forceinline__ uint32_t smem_u32(const void* p) {
    uint32_t a;
    asm("{ .reg .u64 t; cvta.to.shared.u64 t, %1; cvt.u32.u64 %0, t; }" : "=r"(a) : "l"(p));
    return a;
}

#define MBARRIER_INIT(addr, cnt) \
    asm volatile("mbarrier.init.shared.b64 [%0], %1;" :: "r"(addr), "r"(cnt) : "memory")

__device__ __forceinline__ void mbar_expect_tx(uint32_t mbar, uint32_t bytes) {
    asm volatile("mbarrier.arrive.expect_tx.shared.b64 _, [%0], %1;"
                 :: "r"(mbar), "r"(bytes) : "memory");
}

__device__ __forceinline__ void mbar_wait_parity(uint32_t mbar, uint32_t parity) {
    uint32_t done;
    asm volatile(
        "{\n\t.reg .pred p;\n\t"
        "mbarrier.try_wait.parity.shared.b64 p, [%1], %2;\n\t"
        "selp.b32 %0, 1, 0, p;\n\t}"
        : "=r"(done) : "r"(mbar), "r"(parity) : "memory");
    if (!done) {
        asm volatile(
            "{\n\t.reg .pred P1;\n\t"
            "WL_%=:\n\t"
            "mbarrier.try_wait.parity.shared.b64 P1, [%0], %1;\n\t"
            "@P1 bra.uni WD_%=;\n\t"
            "bra.uni WL_%=;\n\t"
            "WD_%=:\n\t}"
            :: "r"(mbar), "r"(parity) : "memory");
    }
}

__device__ __forceinline__ void bulk_g2s(uint32_t dst, const void* src,
                                         uint32_t bytes, uint32_t mbar) {
    asm volatile(
        "cp.async.bulk.shared::cluster.global.mbarrier::complete_tx::bytes "
        "[%0], [%1], %2, [%3];"
        :: "r"(dst), "l"(src), "r"(bytes), "r"(mbar) : "memory");
}

// ----------------------------------------------------------------------------
// Prep kernels: tf32-round x; transpose+round weights to [N][K]
// ----------------------------------------------------------------------------
__global__ void prep_roundx(const float* __restrict__ x, float* __restrict__ xr) {
    int i = blockIdx.x * blockDim.x + threadIdx.x;
    float4 v = *(const float4*)&x[(size_t)i * 4];
    v.x = to_tf32(v.x); v.y = to_tf32(v.y);
    v.z = to_tf32(v.z); v.w = to_tf32(v.w);
    *(float4*)&xr[(size_t)i * 4] = v;
}

__global__ void prep_transpose(const float* __restrict__ wq, const float* __restrict__ wk,
                               const float* __restrict__ wv, const float* __restrict__ wo,
                               float* __restrict__ wqT, float* __restrict__ wkT,
                               float* __restrict__ wvT, float* __restrict__ woT) {
    __shared__ float t[32][33];
    int bid = blockIdx.x;
    const float* src; float* dst; int cols, tb;
    if (bid < 4096)       { src = wq; dst = wqT; cols = 2048; tb = bid; }
    else if (bid < 5120)  { src = wk; dst = wkT; cols = 512;  tb = bid - 4096; }
    else if (bid < 6144)  { src = wv; dst = wvT; cols = 512;  tb = bid - 5120; }
    else                  { src = wo; dst = woT; cols = 2048; tb = bid - 6144; }
    int tpr = cols / 32;
    int k0 = (tb / tpr) * 32;
    int n0 = (tb % tpr) * 32;
    int lr = threadIdx.x >> 5, lc = threadIdx.x & 31;
#pragma unroll
    for (int i = 0; i < 4; i++) {
        int k = k0 + lr + i * 8;
        t[lr + i * 8][lc] = to_tf32(src[(size_t)k * cols + n0 + lc]);
    }
    __syncthreads();
#pragma unroll
    for (int i = 0; i < 4; i++) {
        int n = n0 + lr + i * 8;
        dst[(size_t)n * DIN + k0 + lc] = t[lc][lr + i * 8];
    }
}

// ----------------------------------------------------------------------------
// mma.sync tf32 GEMM, cp.async.bulk staging + ldmatrix (unchanged, passing)
// ----------------------------------------------------------------------------
#define GBK 32
#define GROWB 144
#define G_A_BYTES (128 * GROWB)
#define G_STAGE (2 * G_A_BYTES)
#define G_STAGES 3
#define G_STAGE_TX 32768u
#define GEMM_SMEM (G_STAGES * G_STAGE + 64)

__global__ __launch_bounds__(256, 2)
void gemm_blk_kernel(const float* __restrict__ A,
                     const float* __restrict__ BT0, const float* __restrict__ BT1,
                     const float* __restrict__ BT2,
                     float* __restrict__ out0, float* __restrict__ out1,
                     float* __restrict__ out2,
                     const float* __restrict__ bias, int mode)
{
    extern __shared__ char smp[];
    const uint32_t sbase = smem_u32(smp);
    const uint32_t mbar0 = sbase + G_STAGES * G_STAGE;

    const int tid  = threadIdx.x;
    const int wid  = tid >> 5;
    const int lane = tid & 31;
    const int g    = lane >> 2;
    const int t    = lane & 3;
    const int warp_m = wid & 1;
    const int warp_n = wid >> 1;

    const int row0  = blockIdx.y * 128;
    const int col0g = blockIdx.x * 128;

    const float* BT; float* outp; int Hh, coll;
    if (mode == 1 || col0g < DOUT)  { BT = BT0; outp = out0; Hh = NHEADS; coll = col0g; }
    else if (col0g < DOUT + NKVD)   { BT = BT1; outp = out1; Hh = NKV;    coll = col0g - DOUT; }
    else                            { BT = BT2; outp = out2; Hh = NKV;    coll = col0g - DOUT - NKVD; }

    if (tid == 0) {
#pragma unroll
        for (int s = 0; s < G_STAGES; s++) MBARRIER_INIT(mbar0 + s * 8, 1);
    }
    __syncthreads();

    const int brow = tid & 127;
    const float* gsrcA = &A [(size_t)(row0 + brow) * DIN];
    const float* gsrcB = &BT[(size_t)(coll + brow) * DIN];
    const float* gsrc  = (tid < 128) ? gsrcA : gsrcB;
    const uint32_t dst_off = (tid < 128 ? 0u : (uint32_t)G_A_BYTES) + (uint32_t)brow * GROWB;

    auto issue_bulk = [&](int stage, int kc) {
        bulk_g2s(sbase + stage * G_STAGE + dst_off, gsrc + kc * GBK, 128u,
                 mbar0 + stage * 8);
    };

    const uint32_t offA = (uint32_t)(((lane & 7) + ((lane >> 3) & 1) * 8 + warp_m * 64) * GROWB
                                     + (lane >> 4) * 16);
    const uint32_t offB = (uint32_t)(((lane & 7) + ((lane >> 4) & 1) * 8 + warp_n * 32) * GROWB
                                     + ((lane >> 3) & 1) * 16);

    float c[4][4][4];
#pragma unroll
    for (int i = 0; i < 4; i++)
#pragma unroll
        for (int j = 0; j < 4; j++)
#pragma unroll
            for (int r = 0; r < 4; r++) c[i][j][r] = 0.f;

    if (tid == 0) {
        mbar_expect_tx(mbar0 + 0, G_STAGE_TX);
        mbar_expect_tx(mbar0 + 8, G_STAGE_TX);
    }
    issue_bulk(0, 0);
    issue_bulk(1, 1);

    const int NCH = DIN / GBK;
    for (int kc = 0; kc < NCH; kc++) {
        const int s = kc % 3;
        const uint32_t par = (uint32_t)((kc / 3) & 1);
        mbar_wait_parity(mbar0 + s * 8, par);
        __syncthreads();

        if (kc + 2 < NCH) {
            const int s2 = (kc + 2) % 3;
            if (tid == 0) mbar_expect_tx(mbar0 + s2 * 8, G_STAGE_TX);
            issue_bulk(s2, kc + 2);
        }

        const uint32_t sA = sbase + s * G_STAGE;
        const uint32_t sB = sA + G_A_BYTES;

#pragma unroll
        for (int ks = 0; ks < 4; ks++) {
            const uint32_t kbb = ks * 32;
            uint32_t af[4][4];
#pragma unroll
            for (int mt = 0; mt < 4; mt++)
                ldsm_x4(af[mt][0], af[mt][1], af[mt][2], af[mt][3],
                        sA + offA + mt * (16 * GROWB) + kbb);
            uint32_t bf[4][2];
#pragma unroll
            for (int np = 0; np < 2; np++) {
                uint32_t r0, r1, r2, r3;
                ldsm_x4(r0, r1, r2, r3, sB + offB + np * (16 * GROWB) + kbb);
                bf[2 * np][0] = r0;      bf[2 * np][1] = r1;
                bf[2 * np + 1][0] = r2;  bf[2 * np + 1][1] = r3;
            }
#pragma unroll
            for (int mt = 0; mt < 4; mt++)
#pragma unroll
                for (int nt = 0; nt < 4; nt++)
                    mma_tf32(c[mt][nt], af[mt][0], af[mt][1], af[mt][2], af[mt][3],
                             bf[nt][0], bf[nt][1]);
        }
    }

#pragma unroll
    for (int mt = 0; mt < 4; mt++) {
        int rbase = row0 + warp_m * 64 + mt * 16;
#pragma unroll
        for (int nt = 0; nt < 4; nt++) {
            int cbase = coll + warp_n * 32 + nt * 8;
#pragma unroll
            for (int half = 0; half < 2; half++) {
                int r = rbase + g + half * 8;
                float v0 = c[mt][nt][half * 2 + 0];
                float v1 = c[mt][nt][half * 2 + 1];
                int n0 = cbase + t * 2;
                if (mode == 0) {
                    int b = r >> 11;
                    int s = r & 2047;
                    int h = n0 >> 6;
                    int d = n0 & 63;
                    float* p = &outp[(((size_t)(b * Hh + h)) * SEQ + s) * HD + d];
                    p[0] = v0;
                    p[1] = v1;
                } else {
                    float2 o;
                    o.x = v0 + bias[n0];
                    o.y = v1 + bias[n0 + 1];
                    *(float2*)&outp[(size_t)r * DOUT + n0] = o;
                }
            }
        }
    }
}

// ----------------------------------------------------------------------------
// RoPE + tf32-round: bh 0..63 = q (rope+round), 64..79 = k (rope+round),
// 80..95 = v (round only). Bit-identical to rounding at attention load time.
// ----------------------------------------------------------------------------
__global__ void rope_round_kernel(float* __restrict__ qb, float* __restrict__ kb,
                                  float* __restrict__ vb,
                                  const float* __restrict__ cosT,
                                  const float* __restrict__ sinT)
{
    int idx = blockIdx.x * blockDim.x + threadIdx.x;   // < 96*2048*32
    int d  = idx & 31;
    int s  = (idx >> 5) & (SEQ - 1);
    int bh = idx >> 16;
    if (bh < 80) {
        float* p = (bh < 64) ? qb + ((size_t)bh * SEQ + s) * HD
                             : kb + ((size_t)(bh - 64) * SEQ + s) * HD;
        float t1 = p[d];
        float t2 = p[d + 32];
        float cv = cosT[s * HD + d];
        float sv = sinT[s * HD + d];
        p[d]      = to_tf32(t1 * cv - t2 * sv);
        p[d + 32] = to_tf32(t2 * cv + t1 * sv);
    } else {
        float* p = vb + ((size_t)(bh - 80) * SEQ + s) * HD;
        p[d]      = to_tf32(p[d]);
        p[d + 32] = to_tf32(p[d + 32]);
    }
}

// ----------------------------------------------------------------------------
// Tensor-core flash attention, bulk-staged Q/K/V (pre-rounded by rope pass).
// Register-fragment softmax (round 8). smem: Q,P,K,V tiles + 2 mbarriers.
// ----------------------------------------------------------------------------
#define QPAD  68
#define QPADB 272                       // QPAD*4 bytes
#define ATTN_TILES_BYTES (384 * QPAD * 4)      // 104,448
#define ATTN_SMEM_BYTES (ATTN_TILES_BYTES + 16)

__global__ __launch_bounds__(256, 2)
void attn_tc_kernel(const float* __restrict__ q, const float* __restrict__ k,
                    const float* __restrict__ v, float* __restrict__ ctx)
{
    extern __shared__ float sm[];
    float* Qs = sm;                    // [128][QPAD]
    float* Ps = Qs + 128 * QPAD;       // [128][QPAD]
    float* Vs = Ps + 128 * QPAD;       // [64][QPAD]
    float* Ks = Vs + 64 * QPAD;        // [64][QPAD]
    const uint32_t sbase  = smem_u32(sm);
    const uint32_t qmbar  = sbase + ATTN_TILES_BYTES;
    const uint32_t kvmbar = qmbar + 8;
    const uint32_t Qs_a = sbase;
    const uint32_t Vs_a = sbase + 2u * 128 * QPADB / 1;     // careful below
    // byte offsets
    const uint32_t Ps_b = 128u * QPADB;
    const uint32_t Vs_b = Ps_b + 128u * QPADB;
    const uint32_t Ks_b = Vs_b + 64u * QPADB;

    const int tid  = threadIdx.x;
    const int wid  = tid >> 5;
    const int lane = tid & 31;
    const int g    = lane >> 2;
    const int t    = lane & 3;

    const int bh = blockIdx.y;
    const int b  = bh >> 5;
    const int h  = bh & 31;
    const int kvg = h >> 2;
    const int qi0 = blockIdx.x * 128;
    const int mb  = wid * 16;

    const float* Q = q + ((size_t)(b * NHEADS + h)  * SEQ) * HD;
    const float* K = k + ((size_t)(b * NKV + kvg)   * SEQ) * HD;
    const float* V = v + ((size_t)(b * NKV + kvg)   * SEQ) * HD;

    if (tid == 0) {
        MBARRIER_INIT(qmbar, 128);
        MBARRIER_INIT(kvmbar, 64);
    }
    __syncthreads();

    // Q tile: 128 rows x 256B, one bulk per thread (threads 0-127)
    if (tid < 128) {
        mbar_expect_tx(qmbar, 256);
        bulk_g2s(Qs_a + (uint32_t)tid * QPADB, Q + (size_t)(qi0 + tid) * HD, 256u, qmbar);
    }

    const int row0g = qi0 + mb + g;
    const int row1g = row0g + 8;
    float mi0 = -INFINITY, mi1 = -INFINITY;
    float li0 = 0.f, li1 = 0.f;

    float o[8][4];
#pragma unroll
    for (int n = 0; n < 8; n++)
#pragma unroll
        for (int r = 0; r < 4; r++) o[n][r] = 0.f;

    const int ntiles = 2 * blockIdx.x + 2;
    const float scale = 0.125f;

    bool qwaited = false;

    for (int tt = 0; tt < ntiles; tt++) {
        const int kj0 = tt * 64;
        __syncthreads();   // all warps done reading Ks/Vs of previous tile

        // K/V tiles via bulk: threads 128..191, one K row + one V row each
        if (tid >= 128 && tid < 192) {
            const int r = tid - 128;
            mbar_expect_tx(kvmbar, 512);
            bulk_g2s(sbase + Ks_b + (uint32_t)r * QPADB,
                     K + (size_t)(kj0 + r) * HD, 256u, kvmbar);
            bulk_g2s(sbase + Vs_b + (uint32_t)r * QPADB,
                     V + (size_t)(kj0 + r) * HD, 256u, kvmbar);
        }
        if (!qwaited) { mbar_wait_parity(qmbar, 0); qwaited = true; }
        mbar_wait_parity(kvmbar, (uint32_t)(tt & 1));

        // S = Q K^T : warp's 16x64 strip
        float sfr[8][4];
#pragma unroll
        for (int n = 0; n < 8; n++)
#pragma unroll
            for (int r = 0; r < 4; r++) sfr[n][r] = 0.f;

#pragma unroll
        for (int kk = 0; kk < 8; kk++) {
            const int kb = kk * 8;
            uint32_t a0 = __float_as_uint(Qs[(mb + g    ) * QPAD + kb + t    ]);
            uint32_t a1 = __float_as_uint(Qs[(mb + g + 8) * QPAD + kb + t    ]);
            uint32_t a2 = __float_as_uint(Qs[(mb + g    ) * QPAD + kb + t + 4]);
            uint32_t a3 = __float_as_uint(Qs[(mb + g + 8) * QPAD + kb + t + 4]);
#pragma unroll
            for (int n = 0; n < 8; n++) {
                const int nb = n * 8;
                uint32_t b0 = __float_as_uint(Ks[(nb + g) * QPAD + kb + t    ]);
                uint32_t b1 = __float_as_uint(Ks[(nb + g) * QPAD + kb + t + 4]);
                mma_tf32(sfr[n], a0, a1, a2, a3, b0, b1);
            }
        }

        // Register softmax
        float rm0 = -INFINITY, rm1 = -INFINITY;
#pragma unroll
        for (int n = 0; n < 8; n++) {
            const int c0 = kj0 + n * 8 + 2 * t;
            const int c1 = c0 + 1;
            sfr[n][0] = (c0 <= row0g) ? sfr[n][0] * scale : -INFINITY;
            sfr[n][1] = (c1 <= row0g) ? sfr[n][1] * scale : -INFINITY;
            sfr[n][2] = (c0 <= row1g) ? sfr[n][2] * scale : -INFINITY;
            sfr[n][3] = (c1 <= row1g) ? sfr[n][3] * scale : -INFINITY;
            rm0 = fmaxf(rm0, fmaxf(sfr[n][0], sfr[n][1]));
            rm1 = fmaxf(rm1, fmaxf(sfr[n][2], sfr[n][3]));
        }
        rm0 = fmaxf(rm0, __shfl_xor_sync(0xffffffffu, rm0, 1));
        rm0 = fmaxf(rm0, __shfl_xor_sync(0xffffffffu, rm0, 2));
        rm1 = fmaxf(rm1, __shfl_xor_sync(0xffffffffu, rm1, 1));
        rm1 = fmaxf(rm1, __shfl_xor_sync(0xffffffffu, rm1, 2));

        const float nm0 = fmaxf(mi0, rm0);
        const float nm1 = fmaxf(mi1, rm1);
        const float al0 = __expf(mi0 - nm0);
        const float al1 = __expf(mi1 - nm1);

        float s0 = 0.f, s1 = 0.f;
#pragma unroll
        for (int n = 0; n < 8; n++) {
            float p0 = __expf(sfr[n][0] - nm0);
            float p1 = __expf(sfr[n][1] - nm0);
            float p2 = __expf(sfr[n][2] - nm1);
            float p3 = __expf(sfr[n][3] - nm1);
            s0 += p0 + p1;
            s1 += p2 + p3;
            sfr[n][0] = to_tf32(p0);
            sfr[n][1] = to_tf32(p1);
            sfr[n][2] = to_tf32(p2);
            sfr[n][3] = to_tf32(p3);
        }
        s0 += __shfl_xor_sync(0xffffffffu, s0, 1);
        s0 += __shfl_xor_sync(0xffffffffu, s0, 2);
        s1 += __shfl_xor_sync(0xffffffffu, s1, 1);
        s1 += __shfl_xor_sync(0xffffffffu, s1, 2);

        li0 = li0 * al0 + s0;  mi0 = nm0;
        li1 = li1 * al1 + s1;  mi1 = nm1;

#pragma unroll
        for (int n = 0; n < 8; n++) {
            o[n][0] *= al0; o[n][1] *= al0;
            o[n][2] *= al1; o[n][3] *= al1;
        }

        // Stage P (warp-private strip)
#pragma unroll
        for (int n = 0; n < 8; n++) {
            const int nb = n * 8;
            *(float2*)&Ps[(mb + g    ) * QPAD + nb + 2 * t] = make_float2(sfr[n][0], sfr[n][1]);
            *(float2*)&Ps[(mb + g + 8) * QPAD + nb + 2 * t] = make_float2(sfr[n][2], sfr[n][3]);
        }
        __syncwarp();

        // O += P V
#pragma unroll
        for (int kk = 0; kk < 8; kk++) {
            const int kb = kk * 8;
            uint32_t a0 = __float_as_uint(Ps[(mb + g    ) * QPAD + kb + t    ]);
            uint32_t a1 = __float_as_uint(Ps[(mb + g + 8) * QPAD + kb + t    ]);
            uint32_t a2 = __float_as_uint(Ps[(mb + g    ) * QPAD + kb + t + 4]);
            uint32_t a3 = __float_as_uint(Ps[(mb + g + 8) * QPAD + kb + t + 4]);
#pragma unroll
            for (int n = 0; n < 8; n++) {
                const int nb = n * 8;
                uint32_t b0 = __float_as_uint(Vs[(kb + t    ) * QPAD + nb + g]);
                uint32_t b1 = __float_as_uint(Vs[(kb + t + 4) * QPAD + nb + g]);
                mma_tf32(o[n], a0, a1, a2, a3, b0, b1);
            }
        }
    }

    // Epilogue: normalize, tf32-round, write ctx [b*s, h*64+d]
    {
        const float inv0 = 1.0f / li0;
        const float inv1 = 1.0f / li1;
#pragma unroll
        for (int n = 0; n < 8; n++) {
            int col = h * HD + n * 8 + 2 * t;
            float2 v0 = make_float2(to_tf32(o[n][0] * inv0), to_tf32(o[n][1] * inv0));
            float2 v1 = make_float2(to_tf32(o[n][2] * inv1), to_tf32(o[n][3] * inv1));
            *(float2*)&ctx[((size_t)(b * SEQ + row0g)) * DOUT + col] = v0;
            *(float2*)&ctx[((size_t)(b * SEQ + row1g)) * DOUT + col] = v1;
        }
    }
}

// ----------------------------------------------------------------------------
// Launch.  Inputs: 0:x 1:mask 2:cos 3:sin 4:wq 5:wk 6:wv 7:wo 8:bo
// ----------------------------------------------------------------------------
extern "C" void kernel_launch(void* const* d_in, const int* in_sizes, int n_in,
                              void* d_out, int out_size)
{
    const float* x    = (const float*)d_in[0];
    const float* cosT = (const float*)d_in[2];
    const float* sinT = (const float*)d_in[3];
    const float* wq   = (const float*)d_in[4];
    const float* wk   = (const float*)d_in[5];
    const float* wv   = (const float*)d_in[6];
    const float* wo   = (const float*)d_in[7];
    const float* bo   = (const float*)d_in[8];
    float* out = (float*)d_out;

    float *q, *k, *v, *ctx, *xr, *wqT, *wkT, *wvT, *woT;
    cudaGetSymbolAddress((void**)&q,   g_q);
    cudaGetSymbolAddress((void**)&k,   g_k);
    cudaGetSymbolAddress((void**)&v,   g_v);
    cudaGetSymbolAddress((void**)&ctx, g_ctx);
    cudaGetSymbolAddress((void**)&xr,  g_xr);
    cudaGetSymbolAddress((void**)&wqT, g_wqT);
    cudaGetSymbolAddress((void**)&wkT, g_wkT);
    cudaGetSymbolAddress((void**)&wvT, g_wvT);
    cudaGetSymbolAddress((void**)&woT, g_woT);

    cudaFuncSetAttribute(gemm_blk_kernel,
                         cudaFuncAttributeMaxDynamicSharedMemorySize, GEMM_SMEM);
    cudaFuncSetAttribute(attn_tc_kernel,
                         cudaFuncAttributeMaxDynamicSharedMemorySize, ATTN_SMEM_BYTES);

    // 1-2: Prep (tf32-round x; transpose+round weights)
    prep_roundx<<<(MROWS * DIN / 4) / 256, 256>>>(x, xr);
    prep_transpose<<<10240, 256>>>(wq, wk, wv, wo, wqT, wkT, wvT, woT);

    // 3: Fused QKV projection (bulk-staged mma.sync)
    gemm_blk_kernel<<<dim3((DOUT + 2 * NKVD) / 128, MROWS / 128), 256, GEMM_SMEM>>>(
        xr, wqT, wkT, wvT, q, k, v, nullptr, 0);

    // 4: RoPE + tf32 rounding of q, k, v (single launch)
    rope_round_kernel<<<(96 * SEQ * 32) / 256, 256>>>(q, k, v, cosT, sinT);

    // 5: Tensor-core flash attention (bulk-staged)
    attn_tc_kernel<<<dim3(SEQ / 128, BATCH * NHEADS), 256, ATTN_SMEM_BYTES>>>(q, k, v, ctx);

    // 6: Output projection + bias (bulk-staged mma.sync)
    gemm_blk_kernel<<<dim3(DOUT / 128, MROWS / 128), 256, GEMM_SMEM>>>(
        ctx, woT, nullptr, nullptr, out, nullptr, nullptr, bo, 1);
}

// round 13
// speedup vs baseline: 1.0403x; 1.0403x over previous
#include <cuda_runtime.h>
#include <cuda_bf16.h>
#include <math.h>
#include <stdint.h>

// Problem constants
#define BATCH   2
#define SEQ     2048
#define DIN     2048
#define DOUT    2048
#define NHEADS  32
#define NKV     8
#define HD      64
#define MROWS   (BATCH * SEQ)      // 4096
#define NKVD    (NKV * HD)         // 512

// Scratch (allocation-free rule: __device__ globals)
__device__ float g_q[(size_t)BATCH * NHEADS * SEQ * HD];   // 32MB
__device__ float g_k[(size_t)BATCH * NKV * SEQ * HD];      //  8MB
__device__ float g_v[(size_t)BATCH * NKV * SEQ * HD];      //  8MB
__device__ float g_ctx[(size_t)MROWS * DOUT];              // 32MB (tf32-rounded)
__device__ float g_xr[(size_t)MROWS * DIN];                // 32MB x, tf32-rounded
__device__ float g_wqT[(size_t)DOUT * DIN];                // 16MB [N][K], rounded
__device__ float g_wkT[(size_t)NKVD * DIN];                //  4MB
__device__ float g_wvT[(size_t)NKVD * DIN];                //  4MB
__device__ float g_woT[(size_t)DOUT * DIN];                // 16MB

// ----------------------------------------------------------------------------
// Helpers
// ----------------------------------------------------------------------------
__device__ __forceinline__ float to_tf32(float x) {
    uint32_t u;
    asm("cvt.rna.tf32.f32 %0, %1;" : "=r"(u) : "f"(x));
    return __uint_as_float(u);
}

__device__ __forceinline__ void mma_tf32(float c[4],
                                         uint32_t a0, uint32_t a1, uint32_t a2, uint32_t a3,
                                         uint32_t b0, uint32_t b1) {
    asm volatile(
        "mma.sync.aligned.m16n8k8.row.col.f32.tf32.tf32.f32 "
        "{%0,%1,%2,%3}, {%4,%5,%6,%7}, {%8,%9}, {%0,%1,%2,%3};"
        : "+f"(c[0]), "+f"(c[1]), "+f"(c[2]), "+f"(c[3])
        : "r"(a0), "r"(a1), "r"(a2), "r"(a3), "r"(b0), "r"(b1));
}

__device__ __forceinline__ void ldsm_x4(uint32_t& r0, uint32_t& r1,
                                        uint32_t& r2, uint32_t& r3, uint32_t addr) {
    asm volatile("ldmatrix.sync.aligned.m8n8.x4.shared.b16 {%0,%1,%2,%3}, [%4];"
                 : "=r"(r0), "=r"(r1), "=r"(r2), "=r"(r3) : "r"(addr));
}

__device__ __forceinline__ uint32_t smem_u32(const void* p) {
    uint32_t a;
    asm("{ .reg .u64 t; cvta.to.shared.u64 t, %1; cvt.u32.u64 %0, t; }" : "=r"(a) : "l"(p));
    return a;
}

#define MBARRIER_INIT(addr, cnt) \
    asm volatile("mbarrier.init.shared.b64 [%0], %1;" :: "r"(addr), "r"(cnt) : "memory")

__device__ __forceinline__ void mbar_expect_tx(uint32_t mbar, uint32_t bytes) {
    asm volatile("mbarrier.arrive.expect_tx.shared.b64 _, [%0], %1;"
                 :: "r"(mbar), "r"(bytes) : "memory");
}

__device__ __forceinline__ void mbar_wait_parity(uint32_t mbar, uint32_t parity) {
    uint32_t done;
    asm volatile(
        "{\n\t.reg .pred p;\n\t"
        "mbarrier.try_wait.parity.shared.b64 p, [%1], %2;\n\t"
        "selp.b32 %0, 1, 0, p;\n\t}"
        : "=r"(done) : "r"(mbar), "r"(parity) : "memory");
    if (!done) {
        asm volatile(
            "{\n\t.reg .pred P1;\n\t"
            "WL_%=:\n\t"
            "mbarrier.try_wait.parity.shared.b64 P1, [%0], %1;\n\t"
            "@P1 bra.uni WD_%=;\n\t"
            "bra.uni WL_%=;\n\t"
            "WD_%=:\n\t}"
            :: "r"(mbar), "r"(parity) : "memory");
    }
}

__device__ __forceinline__ void bulk_g2s(uint32_t dst, const void* src,
                                         uint32_t bytes, uint32_t mbar) {
    asm volatile(
        "cp.async.bulk.shared::cluster.global.mbarrier::complete_tx::bytes "
        "[%0], [%1], %2, [%3];"
        :: "r"(dst), "l"(src), "r"(bytes), "r"(mbar) : "memory");
}

// ----------------------------------------------------------------------------
// Prep kernels: tf32-round x; transpose+round weights to [N][K]
// ----------------------------------------------------------------------------
__global__ void prep_roundx(const float* __restrict__ x, float* __restrict__ xr) {
    int i = blockIdx.x * blockDim.x + threadIdx.x;
    float4 v = *(const float4*)&x[(size_t)i * 4];
    v.x = to_tf32(v.x); v.y = to_tf32(v.y);
    v.z = to_tf32(v.z); v.w = to_tf32(v.w);
    *(float4*)&xr[(size_t)i * 4] = v;
}

__global__ void prep_transpose(const float* __restrict__ wq, const float* __restrict__ wk,
                               const float* __restrict__ wv, const float* __restrict__ wo,
                               float* __restrict__ wqT, float* __restrict__ wkT,
                               float* __restrict__ wvT, float* __restrict__ woT) {
    __shared__ float t[32][33];
    int bid = blockIdx.x;
    const float* src; float* dst; int cols, tb;
    if (bid < 4096)       { src = wq; dst = wqT; cols = 2048; tb = bid; }
    else if (bid < 5120)  { src = wk; dst = wkT; cols = 512;  tb = bid - 4096; }
    else if (bid < 6144)  { src = wv; dst = wvT; cols = 512;  tb = bid - 5120; }
    else                  { src = wo; dst = woT; cols = 2048; tb = bid - 6144; }
    int tpr = cols / 32;
    int k0 = (tb / tpr) * 32;
    int n0 = (tb % tpr) * 32;
    int lr = threadIdx.x >> 5, lc = threadIdx.x & 31;
#pragma unroll
    for (int i = 0; i < 4; i++) {
        int k = k0 + lr + i * 8;
        t[lr + i * 8][lc] = to_tf32(src[(size_t)k * cols + n0 + lc]);
    }
    __syncthreads();
#pragma unroll
    for (int i = 0; i < 4; i++) {
        int n = n0 + lr + i * 8;
        dst[(size_t)n * DIN + k0 + lc] = t[lc][lr + i * 8];
    }
}

// ----------------------------------------------------------------------------
// mma.sync tf32 GEMM, cp.async.bulk staging + ldmatrix (unchanged, passing)
// ----------------------------------------------------------------------------
#define GBK 32
#define GROWB 144
#define G_A_BYTES (128 * GROWB)
#define G_STAGE (2 * G_A_BYTES)
#define G_STAGES 3
#define G_STAGE_TX 32768u
#define GEMM_SMEM (G_STAGES * G_STAGE + 64)

__global__ __launch_bounds__(256, 2)
void gemm_blk_kernel(const float* __restrict__ A,
                     const float* __restrict__ BT0, const float* __restrict__ BT1,
                     const float* __restrict__ BT2,
                     float* __restrict__ out0, float* __restrict__ out1,
                     float* __restrict__ out2,
                     const float* __restrict__ bias, int mode)
{
    extern __shared__ char smp[];
    const uint32_t sbase = smem_u32(smp);
    const uint32_t mbar0 = sbase + G_STAGES * G_STAGE;

    const int tid  = threadIdx.x;
    const int wid  = tid >> 5;
    const int lane = tid & 31;
    const int g    = lane >> 2;
    const int t    = lane & 3;
    const int warp_m = wid & 1;
    const int warp_n = wid >> 1;

    const int row0  = blockIdx.y * 128;
    const int col0g = blockIdx.x * 128;

    const float* BT; float* outp; int Hh, coll;
    if (mode == 1 || col0g < DOUT)  { BT = BT0; outp = out0; Hh = NHEADS; coll = col0g; }
    else if (col0g < DOUT + NKVD)   { BT = BT1; outp = out1; Hh = NKV;    coll = col0g - DOUT; }
    else                            { BT = BT2; outp = out2; Hh = NKV;    coll = col0g - DOUT - NKVD; }

    if (tid == 0) {
#pragma unroll
        for (int s = 0; s < G_STAGES; s++) MBARRIER_INIT(mbar0 + s * 8, 1);
    }
    __syncthreads();

    const int brow = tid & 127;
    const float* gsrcA = &A [(size_t)(row0 + brow) * DIN];
    const float* gsrcB = &BT[(size_t)(coll + brow) * DIN];
    const float* gsrc  = (tid < 128) ? gsrcA : gsrcB;
    const uint32_t dst_off = (tid < 128 ? 0u : (uint32_t)G_A_BYTES) + (uint32_t)brow * GROWB;

    auto issue_bulk = [&](int stage, int kc) {
        bulk_g2s(sbase + stage * G_STAGE + dst_off, gsrc + kc * GBK, 128u,
                 mbar0 + stage * 8);
    };

    const uint32_t offA = (uint32_t)(((lane & 7) + ((lane >> 3) & 1) * 8 + warp_m * 64) * GROWB
                                     + (lane >> 4) * 16);
    const uint32_t offB = (uint32_t)(((lane & 7) + ((lane >> 4) & 1) * 8 + warp_n * 32) * GROWB
                                     + ((lane >> 3) & 1) * 16);

    float c[4][4][4];
#pragma unroll
    for (int i = 0; i < 4; i++)
#pragma unroll
        for (int j = 0; j < 4; j++)
#pragma unroll
            for (int r = 0; r < 4; r++) c[i][j][r] = 0.f;

    if (tid == 0) {
        mbar_expect_tx(mbar0 + 0, G_STAGE_TX);
        mbar_expect_tx(mbar0 + 8, G_STAGE_TX);
    }
    issue_bulk(0, 0);
    issue_bulk(1, 1);

    const int NCH = DIN / GBK;
    for (int kc = 0; kc < NCH; kc++) {
        const int s = kc % 3;
        const uint32_t par = (uint32_t)((kc / 3) & 1);
        mbar_wait_parity(mbar0 + s * 8, par);
        __syncthreads();

        if (kc + 2 < NCH) {
            const int s2 = (kc + 2) % 3;
            if (tid == 0) mbar_expect_tx(mbar0 + s2 * 8, G_STAGE_TX);
            issue_bulk(s2, kc + 2);
        }

        const uint32_t sA = sbase + s * G_STAGE;
        const uint32_t sB = sA + G_A_BYTES;

#pragma unroll
        for (int ks = 0; ks < 4; ks++) {
            const uint32_t kbb = ks * 32;
            uint32_t af[4][4];
#pragma unroll
            for (int mt = 0; mt < 4; mt++)
                ldsm_x4(af[mt][0], af[mt][1], af[mt][2], af[mt][3],
                        sA + offA + mt * (16 * GROWB) + kbb);
            uint32_t bf[4][2];
#pragma unroll
            for (int np = 0; np < 2; np++) {
                uint32_t r0, r1, r2, r3;
                ldsm_x4(r0, r1, r2, r3, sB + offB + np * (16 * GROWB) + kbb);
                bf[2 * np][0] = r0;      bf[2 * np][1] = r1;
                bf[2 * np + 1][0] = r2;  bf[2 * np + 1][1] = r3;
            }
#pragma unroll
            for (int mt = 0; mt < 4; mt++)
#pragma unroll
                for (int nt = 0; nt < 4; nt++)
                    mma_tf32(c[mt][nt], af[mt][0], af[mt][1], af[mt][2], af[mt][3],
                             bf[nt][0], bf[nt][1]);
        }
    }

#pragma unroll
    for (int mt = 0; mt < 4; mt++) {
        int rbase = row0 + warp_m * 64 + mt * 16;
#pragma unroll
        for (int nt = 0; nt < 4; nt++) {
            int cbase = coll + warp_n * 32 + nt * 8;
#pragma unroll
            for (int half = 0; half < 2; half++) {
                int r = rbase + g + half * 8;
                float v0 = c[mt][nt][half * 2 + 0];
                float v1 = c[mt][nt][half * 2 + 1];
                int n0 = cbase + t * 2;
                if (mode == 0) {
                    int b = r >> 11;
                    int s = r & 2047;
                    int h = n0 >> 6;
                    int d = n0 & 63;
                    float* p = &outp[(((size_t)(b * Hh + h)) * SEQ + s) * HD + d];
                    p[0] = v0;
                    p[1] = v1;
                } else {
                    float2 o;
                    o.x = v0 + bias[n0];
                    o.y = v1 + bias[n0 + 1];
                    *(float2*)&outp[(size_t)r * DOUT + n0] = o;
                }
            }
        }
    }
}

// ----------------------------------------------------------------------------
// RoPE + tf32-round: bh 0..63 = q (rope+round), 64..79 = k (rope+round),
// 80..95 = v (round only). Bit-identical to rounding at attention load time.
// ----------------------------------------------------------------------------
__global__ void rope_round_kernel(float* __restrict__ qb, float* __restrict__ kb,
                                  float* __restrict__ vb,
                                  const float* __restrict__ cosT,
                                  const float* __restrict__ sinT)
{
    int idx = blockIdx.x * blockDim.x + threadIdx.x;   // < 96*2048*32
    int d  = idx & 31;
    int s  = (idx >> 5) & (SEQ - 1);
    int bh = idx >> 16;
    if (bh < 80) {
        float* p = (bh < 64) ? qb + ((size_t)bh * SEQ + s) * HD
                             : kb + ((size_t)(bh - 64) * SEQ + s) * HD;
        float t1 = p[d];
        float t2 = p[d + 32];
        float cv = cosT[s * HD + d];
        float sv = sinT[s * HD + d];
        p[d]      = to_tf32(t1 * cv - t2 * sv);
        p[d + 32] = to_tf32(t2 * cv + t1 * sv);
    } else {
        float* p = vb + ((size_t)(bh - 80) * SEQ + s) * HD;
        p[d]      = to_tf32(p[d]);
        p[d + 32] = to_tf32(p[d + 32]);
    }
}

// ----------------------------------------------------------------------------
// Tensor-core flash attention (round-11 LDG/STS staging — occupancy-2 latency
// hiding — now cvt-free since q/k/v are pre-rounded by rope_round_kernel).
// Register-fragment softmax. Grid: (SEQ/128, BATCH*NHEADS).
// ----------------------------------------------------------------------------
#define QPAD 68
#define ATTN_SMEM_BYTES ((384 * QPAD) * 4)

__global__ __launch_bounds__(256, 2)
void attn_tc_kernel(const float* __restrict__ q, const float* __restrict__ k,
                    const float* __restrict__ v, float* __restrict__ ctx)
{
    extern __shared__ float sm[];
    float* Qs = sm;                    // [128][QPAD]
    float* Ps = Qs + 128 * QPAD;       // [128][QPAD]
    float* Ks = Ps + 128 * QPAD;       // [64][QPAD]
    float* Vs = Ks + 64 * QPAD;        // [64][QPAD]

    const int tid  = threadIdx.x;
    const int wid  = tid >> 5;
    const int lane = tid & 31;
    const int g    = lane >> 2;
    const int t    = lane & 3;

    const int bh = blockIdx.y;
    const int b  = bh >> 5;
    const int h  = bh & 31;
    const int kvg = h >> 2;
    const int qi0 = blockIdx.x * 128;
    const int mb  = wid * 16;

    const float* Q = q + ((size_t)(b * NHEADS + h)  * SEQ) * HD;
    const float* K = k + ((size_t)(b * NKV + kvg)   * SEQ) * HD;
    const float* V = v + ((size_t)(b * NKV + kvg)   * SEQ) * HD;

    // Load Q tile (pre-rounded; no cvt)
#pragma unroll
    for (int r = 0; r < 8; r++) {
        int idx = tid + r * 256;
        int qr = idx >> 4;
        int c4 = idx & 15;
        *(float4*)&Qs[qr * QPAD + c4 * 4] =
            *(const float4*)&Q[(size_t)(qi0 + qr) * HD + c4 * 4];
    }

    const int row0g = qi0 + mb + g;
    const int row1g = row0g + 8;
    float mi0 = -INFINITY, mi1 = -INFINITY;
    float li0 = 0.f, li1 = 0.f;

    float o[8][4];
#pragma unroll
    for (int n = 0; n < 8; n++)
#pragma unroll
        for (int r = 0; r < 4; r++) o[n][r] = 0.f;

    const int ntiles = 2 * blockIdx.x + 2;
    const float scale = 0.125f;

    for (int tt = 0; tt < ntiles; tt++) {
        const int kj0 = tt * 64;
        __syncthreads();   // all warps done reading Ks/Vs of previous tile

        // Load K and V tiles (pre-rounded; no cvt)
#pragma unroll
        for (int r = 0; r < 4; r++) {
            int idx = tid + r * 256;
            int kr = idx >> 4;
            int c4 = idx & 15;
            *(float4*)&Ks[kr * QPAD + c4 * 4] =
                *(const float4*)&K[(size_t)(kj0 + kr) * HD + c4 * 4];
            *(float4*)&Vs[kr * QPAD + c4 * 4] =
                *(const float4*)&V[(size_t)(kj0 + kr) * HD + c4 * 4];
        }
        __syncthreads();

        // S = Q K^T : warp's 16x64 strip
        float sfr[8][4];
#pragma unroll
        for (int n = 0; n < 8; n++)
#pragma unroll
            for (int r = 0; r < 4; r++) sfr[n][r] = 0.f;

#pragma unroll
        for (int kk = 0; kk < 8; kk++) {
            const int kb = kk * 8;
            uint32_t a0 = __float_as_uint(Qs[(mb + g    ) * QPAD + kb + t    ]);
            uint32_t a1 = __float_as_uint(Qs[(mb + g + 8) * QPAD + kb + t    ]);
            uint32_t a2 = __float_as_uint(Qs[(mb + g    ) * QPAD + kb + t + 4]);
            uint32_t a3 = __float_as_uint(Qs[(mb + g + 8) * QPAD + kb + t + 4]);
#pragma unroll
            for (int n = 0; n < 8; n++) {
                const int nb = n * 8;
                uint32_t b0 = __float_as_uint(Ks[(nb + g) * QPAD + kb + t    ]);
                uint32_t b1 = __float_as_uint(Ks[(nb + g) * QPAD + kb + t + 4]);
                mma_tf32(sfr[n], a0, a1, a2, a3, b0, b1);
            }
        }

        // Register softmax
        float rm0 = -INFINITY, rm1 = -INFINITY;
#pragma unroll
        for (int n = 0; n < 8; n++) {
            const int c0 = kj0 + n * 8 + 2 * t;
            const int c1 = c0 + 1;
            sfr[n][0] = (c0 <= row0g) ? sfr[n][0] * scale : -INFINITY;
            sfr[n][1] = (c1 <= row0g) ? sfr[n][1] * scale : -INFINITY;
            sfr[n][2] = (c0 <= row1g) ? sfr[n][2] * scale : -INFINITY;
            sfr[n][3] = (c1 <= row1g) ? sfr[n][3] * scale : -INFINITY;
            rm0 = fmaxf(rm0, fmaxf(sfr[n][0], sfr[n][1]));
            rm1 = fmaxf(rm1, fmaxf(sfr[n][2], sfr[n][3]));
        }
        rm0 = fmaxf(rm0, __shfl_xor_sync(0xffffffffu, rm0, 1));
        rm0 = fmaxf(rm0, __shfl_xor_sync(0xffffffffu, rm0, 2));
        rm1 = fmaxf(rm1, __shfl_xor_sync(0xffffffffu, rm1, 1));
        rm1 = fmaxf(rm1, __shfl_xor_sync(0xffffffffu, rm1, 2));

        const float nm0 = fmaxf(mi0, rm0);
        const float nm1 = fmaxf(mi1, rm1);
        const float al0 = __expf(mi0 - nm0);
        const float al1 = __expf(mi1 - nm1);

        float s0 = 0.f, s1 = 0.f;
#pragma unroll
        for (int n = 0; n < 8; n++) {
            float p0 = __expf(sfr[n][0] - nm0);
            float p1 = __expf(sfr[n][1] - nm0);
            float p2 = __expf(sfr[n][2] - nm1);
            float p3 = __expf(sfr[n][3] - nm1);
            s0 += p0 + p1;
            s1 += p2 + p3;
            sfr[n][0] = to_tf32(p0);
            sfr[n][1] = to_tf32(p1);
            sfr[n][2] = to_tf32(p2);
            sfr[n][3] = to_tf32(p3);
        }
        s0 += __shfl_xor_sync(0xffffffffu, s0, 1);
        s0 += __shfl_xor_sync(0xffffffffu, s0, 2);
        s1 += __shfl_xor_sync(0xffffffffu, s1, 1);
        s1 += __shfl_xor_sync(0xffffffffu, s1, 2);

        li0 = li0 * al0 + s0;  mi0 = nm0;
        li1 = li1 * al1 + s1;  mi1 = nm1;

#pragma unroll
        for (int n = 0; n < 8; n++) {
            o[n][0] *= al0; o[n][1] *= al0;
            o[n][2] *= al1; o[n][3] *= al1;
        }

        // Stage P (warp-private strip)
#pragma unroll
        for (int n = 0; n < 8; n++) {
            const int nb = n * 8;
            *(float2*)&Ps[(mb + g    ) * QPAD + nb + 2 * t] = make_float2(sfr[n][0], sfr[n][1]);
            *(float2*)&Ps[(mb + g + 8) * QPAD + nb + 2 * t] = make_float2(sfr[n][2], sfr[n][3]);
        }
        __syncwarp();

        // O += P V
#pragma unroll
        for (int kk = 0; kk < 8; kk++) {
            const int kb = kk * 8;
            uint32_t a0 = __float_as_uint(Ps[(mb + g    ) * QPAD + kb + t    ]);
            uint32_t a1 = __float_as_uint(Ps[(mb + g + 8) * QPAD + kb + t    ]);
            uint32_t a2 = __float_as_uint(Ps[(mb + g    ) * QPAD + kb + t + 4]);
            uint32_t a3 = __float_as_uint(Ps[(mb + g + 8) * QPAD + kb + t + 4]);
#pragma unroll
            for (int n = 0; n < 8; n++) {
                const int nb = n * 8;
                uint32_t b0 = __float_as_uint(Vs[(kb + t    ) * QPAD + nb + g]);
                uint32_t b1 = __float_as_uint(Vs[(kb + t + 4) * QPAD + nb + g]);
                mma_tf32(o[n], a0, a1, a2, a3, b0, b1);
            }
        }
    }

    // Epilogue: normalize, tf32-round, write ctx [b*s, h*64+d]
    {
        const float inv0 = 1.0f / li0;
        const float inv1 = 1.0f / li1;
#pragma unroll
        for (int n = 0; n < 8; n++) {
            int col = h * HD + n * 8 + 2 * t;
            float2 v0 = make_float2(to_tf32(o[n][0] * inv0), to_tf32(o[n][1] * inv0));
            float2 v1 = make_float2(to_tf32(o[n][2] * inv1), to_tf32(o[n][3] * inv1));
            *(float2*)&ctx[((size_t)(b * SEQ + row0g)) * DOUT + col] = v0;
            *(float2*)&ctx[((size_t)(b * SEQ + row1g)) * DOUT + col] = v1;
        }
    }
}

// ----------------------------------------------------------------------------
// Launch.  Inputs: 0:x 1:mask 2:cos 3:sin 4:wq 5:wk 6:wv 7:wo 8:bo
// ----------------------------------------------------------------------------
extern "C" void kernel_launch(void* const* d_in, const int* in_sizes, int n_in,
                              void* d_out, int out_size)
{
    const float* x    = (const float*)d_in[0];
    const float* cosT = (const float*)d_in[2];
    const float* sinT = (const float*)d_in[3];
    const float* wq   = (const float*)d_in[4];
    const float* wk   = (const float*)d_in[5];
    const float* wv   = (const float*)d_in[6];
    const float* wo   = (const float*)d_in[7];
    const float* bo   = (const float*)d_in[8];
    float* out = (float*)d_out;

    float *q, *k, *v, *ctx, *xr, *wqT, *wkT, *wvT, *woT;
    cudaGetSymbolAddress((void**)&q,   g_q);
    cudaGetSymbolAddress((void**)&k,   g_k);
    cudaGetSymbolAddress((void**)&v,   g_v);
    cudaGetSymbolAddress((void**)&ctx, g_ctx);
    cudaGetSymbolAddress((void**)&xr,  g_xr);
    cudaGetSymbolAddress((void**)&wqT, g_wqT);
    cudaGetSymbolAddress((void**)&wkT, g_wkT);
    cudaGetSymbolAddress((void**)&wvT, g_wvT);
    cudaGetSymbolAddress((void**)&woT, g_woT);

    cudaFuncSetAttribute(gemm_blk_kernel,
                         cudaFuncAttributeMaxDynamicSharedMemorySize, GEMM_SMEM);
    cudaFuncSetAttribute(attn_tc_kernel,
                         cudaFuncAttributeMaxDynamicSharedMemorySize, ATTN_SMEM_BYTES);

    // 1-2: Prep (tf32-round x; transpose+round weights)
    prep_roundx<<<(MROWS * DIN / 4) / 256, 256>>>(x, xr);
    prep_transpose<<<10240, 256>>>(wq, wk, wv, wo, wqT, wkT, wvT, woT);

    // 3: Fused QKV projection (bulk-staged mma.sync)
    gemm_blk_kernel<<<dim3((DOUT + 2 * NKVD) / 128, MROWS / 128), 256, GEMM_SMEM>>>(
        xr, wqT, wkT, wvT, q, k, v, nullptr, 0);

    // 4: RoPE + tf32 rounding of q, k, v (single launch)
    rope_round_kernel<<<(96 * SEQ * 32) / 256, 256>>>(q, k, v, cosT, sinT);

    // 5: Tensor-core flash attention (LDG/STS staging, occupancy 2)
    attn_tc_kernel<<<dim3(SEQ / 128, BATCH * NHEADS), 256, ATTN_SMEM_BYTES>>>(q, k, v, ctx);

    // 6: Output projection + bias (bulk-staged mma.sync)
    gemm_blk_kernel<<<dim3(DOUT / 128, MROWS / 128), 256, GEMM_SMEM>>>(
        ctx, woT, nullptr, nullptr, out, nullptr, nullptr, bo, 1);
}